// round 12
// baseline (speedup 1.0000x reference)
#include <cuda_runtime.h>
#include <cuda_bf16.h>
#include <cstdint>

#define BATCH 8
#define NPTS  8192
#define NQ    2048
#define NK    32
#define NF    16

// Output layout: flattened float32 concat of the 5-tuple
static const size_t QP_OFF  = 0;                                   // 8*2048*3      = 49152
static const size_t GF_OFF  = 49152;                               // 8*2048*32*19  = 9961472
static const size_t IDX_OFF = 49152 + 9961472;                     // 10,010,624
static const size_t GPN_OFF = IDX_OFF + (size_t)BATCH*NQ*NK;       // 10,534,912
static const size_t GP_OFF  = GPN_OFF + (size_t)BATCH*NQ*NK*3;     // 12,107,776

__device__ float g_sx[BATCH * NPTS];
__device__ float g_sy[BATCH * NPTS];
__device__ float g_sz[BATCH * NPTS];

// ---- packed f32x2 helpers (sm_103a): per-lane IEEE .rn, identical to scalar
typedef unsigned long long u64;
__device__ __forceinline__ u64 pack2(float lo, float hi) {
    u64 r; asm("mov.b64 %0, {%1, %2};" : "=l"(r) : "f"(lo), "f"(hi)); return r;
}
__device__ __forceinline__ void unpack2(u64 v, float& lo, float& hi) {
    asm("mov.b64 {%0, %1}, %2;" : "=f"(lo), "=f"(hi) : "l"(v));
}
__device__ __forceinline__ u64 add2(u64 a, u64 b) {
    u64 r; asm("add.rn.f32x2 %0, %1, %2;" : "=l"(r) : "l"(a), "l"(b)); return r;
}
__device__ __forceinline__ u64 mul2(u64 a, u64 b) {
    u64 r; asm("mul.rn.f32x2 %0, %1, %2;" : "=l"(r) : "l"(a), "l"(b)); return r;
}
__device__ __forceinline__ float fneg_exact(float x) {   // sign-bit flip (ALU)
    return __uint_as_float(__float_as_uint(x) ^ 0x80000000u);
}

// ---------------------------------------------------------------------------
// Kernel 0: AoS -> SoA transpose of points (one-time, ~5us).
// ---------------------------------------------------------------------------
__global__ void __launch_bounds__(256)
transpose_kernel(const float* __restrict__ pts)
{
    const int i = blockIdx.x * blockDim.x + threadIdx.x;
    if (i >= BATCH * NPTS) return;
    g_sx[i] = pts[(size_t)i * 3 + 0];
    g_sy[i] = pts[(size_t)i * 3 + 1];
    g_sz[i] = pts[(size_t)i * 3 + 2];
}

// ---------------------------------------------------------------------------
// Kernel 1: farthest point sampling — R11 structure, with the serial 16-deep
// fmax chain replaced by a balanced tree (depth ~16 cyc instead of 64 on the
// per-iteration critical path). Same operand multiset -> same max value;
// owner/tie-break logic untouched.
// 512 threads x 16 pts/thread packed f32x2. Exact semantics: d =
// ((dx*dx)+(dy*dy))+(dz*dz), each op .rn (no FMA), dist=min(dist,d),
// argmax first-index tie-break:
//   REDUX.max -> lane0 atomicMax(s_gmax[buf]); bar1; owners (ut==g) resolve
//   first-j, atomicMin(s_best[buf]); t0 resets spares; bar2; all threads
//   LDG-broadcast pts[best] (uniform address, L1-resident).
// ---------------------------------------------------------------------------
__global__ void __launch_bounds__(512, 1)
fps_kernel(const float* __restrict__ pts, float* __restrict__ out_qp)
{
    const int b = blockIdx.x;
    const int t = threadIdx.x;
    const float* p = pts + (size_t)b * NPTS * 3;

    __shared__ unsigned s_gmax[2];
    __shared__ int      s_best[2];

    u64 PX[8], PY[8], PZ[8];
    float dist[16];
#pragma unroll
    for (int pr = 0; pr < 8; pr++) {
        int i0 = t * 16 + pr * 2;
        float x0 = p[i0 * 3 + 0], y0 = p[i0 * 3 + 1], z0 = p[i0 * 3 + 2];
        float x1 = p[i0 * 3 + 3], y1 = p[i0 * 3 + 4], z1 = p[i0 * 3 + 5];
        PX[pr] = pack2(x0, x1); PY[pr] = pack2(y0, y1); PZ[pr] = pack2(z0, z1);
        dist[pr * 2] = 1e10f; dist[pr * 2 + 1] = 1e10f;
    }
    float cx = __ldg(p + 0), cy = __ldg(p + 1), cz = __ldg(p + 2);
    if (t == 0) {
        s_gmax[0] = 0u; s_gmax[1] = 0u;
        s_best[0] = 0x7fffffff; s_best[1] = 0x7fffffff;
        float* o = out_qp + (size_t)b * NQ * 3;
        o[0] = cx; o[1] = cy; o[2] = cz;
    }
    __syncthreads();

    for (int it = 1; it < NQ; ++it) {
        const int buf = it & 1;
        const float nx = fneg_exact(cx), ny = fneg_exact(cy), nz = fneg_exact(cz);
        const u64 nx2 = pack2(nx, nx);
        const u64 ny2 = pack2(ny, ny);
        const u64 nz2 = pack2(nz, nz);

        float pm[8];
#pragma unroll
        for (int pr = 0; pr < 8; pr++) {
            u64 dx2 = add2(PX[pr], nx2);            // x + (-c) == x - c exactly
            u64 dy2 = add2(PY[pr], ny2);
            u64 dz2 = add2(PZ[pr], nz2);
            u64 d2  = add2(add2(mul2(dx2, dx2), mul2(dy2, dy2)), mul2(dz2, dz2));
            float d0, d1; unpack2(d2, d0, d1);
            float n0 = fminf(dist[pr * 2 + 0], d0);
            float n1 = fminf(dist[pr * 2 + 1], d1);
            dist[pr * 2 + 0] = n0; dist[pr * 2 + 1] = n1;
            pm[pr] = fmaxf(n0, n1);
        }
        // balanced max tree (depth 3 after per-pair max)
        pm[0] = fmaxf(pm[0], pm[4]);
        pm[1] = fmaxf(pm[1], pm[5]);
        pm[2] = fmaxf(pm[2], pm[6]);
        pm[3] = fmaxf(pm[3], pm[7]);
        pm[0] = fmaxf(pm[0], pm[2]);
        pm[1] = fmaxf(pm[1], pm[3]);
        const float tmax = fmaxf(pm[0], pm[1]);

        const unsigned ut = __float_as_uint(tmax);
        const unsigned wm = __reduce_max_sync(0xffffffffu, ut);
        if ((t & 31) == 0) atomicMax(&s_gmax[buf], wm);
        __syncthreads();                            // bar1: gmax final

        const unsigned g = s_gmax[buf];
        if (ut == g) {                              // owner thread(s): rare
            int j = 0;
#pragma unroll
            for (int jj = 15; jj >= 0; jj--)        // downward => first match
                if (__float_as_uint(dist[jj]) == g) j = jj;
            atomicMin(&s_best[buf], t * 16 + j);
        }
        if (t == 0) { s_gmax[buf ^ 1] = 0u; s_best[buf ^ 1] = 0x7fffffff; }
        __syncthreads();                            // bar2: best final

        const int best = s_best[buf];
        const float* pb = p + (size_t)best * 3;     // uniform -> L1 broadcast
        cx = __ldg(pb + 0); cy = __ldg(pb + 1); cz = __ldg(pb + 2);
        if (t == 0) {
            float* o = out_qp + ((size_t)b * NQ + it) * 3;
            o[0] = cx; o[1] = cy; o[2] = cz;
        }
    }
}

// ---------------------------------------------------------------------------
// Kernel 2: FUSED ball query + gather. One warp per query.
// Scan: no early exit (deep MLP), ballot + prefix-popc in-order hit collect,
// exact arithmetic (plain subtract; __fmul_rn/__fadd_rn sum, no FMA).
// R2 = float(double(0.1*0.1)) matches the weakly-typed JAX scalar.
// Gather runs inline on the indices still in smem/registers; grouped_features
// staged through shared (stride 19 conflict-free) and stored coalesced.
// ---------------------------------------------------------------------------
__global__ void __launch_bounds__(256)
ball_gather_kernel(const float* __restrict__ qp, const float* __restrict__ feat,
                   float* __restrict__ out)
{
    const int warp = threadIdx.x >> 5;
    const int lane = threadIdx.x & 31;
    const int gq   = blockIdx.x * 8 + warp;        // one query per warp
    const int b    = gq >> 11;                     // gq / NQ
    const float R2 = (float)(0.1 * 0.1);           // 0.00999999977648258f
    const float* sx = g_sx + (size_t)b * NPTS;
    const float* sy = g_sy + (size_t)b * NPTS;
    const float* sz = g_sz + (size_t)b * NPTS;

    __shared__ int   s_wi[8][NK];
    __shared__ float s[8][NK * 19];

    const float qx = qp[(size_t)gq * 3 + 0];
    const float qy = qp[(size_t)gq * 3 + 1];
    const float qz = qp[(size_t)gq * 3 + 2];

    int cnt = 0;
    const unsigned lmask = (1u << lane) - 1u;
#pragma unroll 4
    for (int c = 0; c < NPTS / 32; c++) {
        const int i = c * 32 + lane;
        float dx = qx - __ldg(sx + i);
        float dy = qy - __ldg(sy + i);
        float dz = qz - __ldg(sz + i);
        float d  = __fadd_rn(__fadd_rn(__fmul_rn(dx, dx), __fmul_rn(dy, dy)),
                             __fmul_rn(dz, dz));
        const bool in = (d <= R2);
        const unsigned m = __ballot_sync(0xffffffffu, in);
        if (m) {
            const int slot = cnt + __popc(m & lmask);
            if (in && slot < NK) s_wi[warp][slot] = i;
            cnt += __popc(m);
        }
    }
    __syncwarp();
    const int cf    = cnt < NK ? cnt : NK;
    const int first = s_wi[warp][0];
    const int idx   = (lane < cf) ? s_wi[warp][lane] : first;

    out[IDX_OFF + (size_t)gq * NK + lane] = (float)idx;

    // ---- inline gather (lane = k) ----
    const size_t pb = (size_t)b * NPTS + idx;
    const float px = sx[idx];
    const float py = sy[idx];
    const float pz = sz[idx];
    const float nx = px - qx, ny = py - qy, nz = pz - qz;

    const float4* f4 = (const float4*)(feat + pb * NF);
    const float4 f0 = f4[0], f1 = f4[1], f2 = f4[2], f3 = f4[3];

    float* sw = &s[warp][lane * 19];
    sw[0]  = nx;   sw[1]  = ny;   sw[2]  = nz;
    sw[3]  = f0.x; sw[4]  = f0.y; sw[5]  = f0.z; sw[6]  = f0.w;
    sw[7]  = f1.x; sw[8]  = f1.y; sw[9]  = f1.z; sw[10] = f1.w;
    sw[11] = f2.x; sw[12] = f2.y; sw[13] = f2.z; sw[14] = f2.w;
    sw[15] = f3.x; sw[16] = f3.y; sw[17] = f3.z; sw[18] = f3.w;
    __syncwarp();

    float* gf = out + GF_OFF + (size_t)gq * (NK * 19);
#pragma unroll
    for (int w = 0; w < 19; w++) {
        const int i = w * 32 + lane;
        gf[i] = s[warp][i];                           // coalesced
    }

    float* gpn = out + GPN_OFF + ((size_t)gq * NK + lane) * 3;
    gpn[0] = nx; gpn[1] = ny; gpn[2] = nz;

    float* gp = out + GP_OFF + ((size_t)gq * NK + lane) * 3;
    gp[0] = px; gp[1] = py; gp[2] = pz;
}

// ---------------------------------------------------------------------------
extern "C" void kernel_launch(void* const* d_in, const int* in_sizes, int n_in,
                              void* d_out, int out_size)
{
    const float* points   = (const float*)d_in[0];
    const float* features = (const float*)d_in[1];
    if (in_sizes[0] != BATCH * NPTS * 3) {
        const float* tmp = points; points = features; features = tmp;
    }
    float* out = (float*)d_out;

    transpose_kernel<<<(BATCH * NPTS + 255) / 256, 256>>>(points);
    fps_kernel<<<BATCH, 512>>>(points, out + QP_OFF);
    ball_gather_kernel<<<BATCH * NQ / 8, 256>>>(out + QP_OFF, features, out);
}

// round 13
// speedup vs baseline: 1.0738x; 1.0738x over previous
#include <cuda_runtime.h>
#include <cuda_bf16.h>
#include <cstdint>

#define BATCH 8
#define NPTS  8192
#define NQ    2048
#define NK    32
#define NF    16

// Output layout: flattened float32 concat of the 5-tuple
static const size_t QP_OFF  = 0;                                   // 8*2048*3      = 49152
static const size_t GF_OFF  = 49152;                               // 8*2048*32*19  = 9961472
static const size_t IDX_OFF = 49152 + 9961472;                     // 10,010,624
static const size_t GPN_OFF = IDX_OFF + (size_t)BATCH*NQ*NK;       // 10,534,912
static const size_t GP_OFF  = GPN_OFF + (size_t)BATCH*NQ*NK*3;     // 12,107,776

__device__ int   g_nidx[BATCH * NQ * NK];
__device__ float g_sx[BATCH * NPTS];
__device__ float g_sy[BATCH * NPTS];
__device__ float g_sz[BATCH * NPTS];

// ---- packed f32x2 helpers (sm_103a): per-lane IEEE .rn, identical to scalar
typedef unsigned long long u64;
__device__ __forceinline__ u64 pack2(float lo, float hi) {
    u64 r; asm("mov.b64 %0, {%1, %2};" : "=l"(r) : "f"(lo), "f"(hi)); return r;
}
__device__ __forceinline__ void unpack2(u64 v, float& lo, float& hi) {
    asm("mov.b64 {%0, %1}, %2;" : "=f"(lo), "=f"(hi) : "l"(v));
}
__device__ __forceinline__ u64 add2(u64 a, u64 b) {
    u64 r; asm("add.rn.f32x2 %0, %1, %2;" : "=l"(r) : "l"(a), "l"(b)); return r;
}
__device__ __forceinline__ u64 mul2(u64 a, u64 b) {
    u64 r; asm("mul.rn.f32x2 %0, %1, %2;" : "=l"(r) : "l"(a), "l"(b)); return r;
}
__device__ __forceinline__ float fneg_exact(float x) {   // sign-bit flip (ALU)
    return __uint_as_float(__float_as_uint(x) ^ 0x80000000u);
}

// ---------------------------------------------------------------------------
// Kernel 0: AoS -> SoA transpose of points (one-time, ~4.5us).
// ---------------------------------------------------------------------------
__global__ void __launch_bounds__(256)
transpose_kernel(const float* __restrict__ pts)
{
    const int i = blockIdx.x * blockDim.x + threadIdx.x;
    if (i >= BATCH * NPTS) return;
    g_sx[i] = pts[(size_t)i * 3 + 0];
    g_sy[i] = pts[(size_t)i * 3 + 1];
    g_sz[i] = pts[(size_t)i * 3 + 2];
}

// ---------------------------------------------------------------------------
// Kernel 1: farthest point sampling — R11 reduction structure (proven), one
// more step of the measured geometry trend: 256 threads x 32 pts/thread
// (fma drain invariant; atomic round, barrier skew, loop overhead halve).
// Exact semantics: d = ((dx*dx)+(dy*dy))+(dz*dz), each op .rn (no FMA),
// dist = min(dist, d), argmax with first-index tie-break:
//   REDUX.max -> lane0 atomicMax(s_gmax[buf]); bar1; owners (ut==g) resolve
//   first-j, atomicMin(s_best[buf]); t0 resets spares; bar2; all threads
//   LDG-broadcast pts[best] (uniform address, L1-resident).
// ---------------------------------------------------------------------------
__global__ void __launch_bounds__(256, 1)
fps_kernel(const float* __restrict__ pts, float* __restrict__ out_qp)
{
    const int b = blockIdx.x;
    const int t = threadIdx.x;
    const float* p = pts + (size_t)b * NPTS * 3;

    __shared__ unsigned s_gmax[2];
    __shared__ int      s_best[2];

    u64 PX[16], PY[16], PZ[16];
    float dist[32];
#pragma unroll
    for (int pr = 0; pr < 16; pr++) {
        int i0 = t * 32 + pr * 2;
        float x0 = p[i0 * 3 + 0], y0 = p[i0 * 3 + 1], z0 = p[i0 * 3 + 2];
        float x1 = p[i0 * 3 + 3], y1 = p[i0 * 3 + 4], z1 = p[i0 * 3 + 5];
        PX[pr] = pack2(x0, x1); PY[pr] = pack2(y0, y1); PZ[pr] = pack2(z0, z1);
        dist[pr * 2] = 1e10f; dist[pr * 2 + 1] = 1e10f;
    }
    float cx = __ldg(p + 0), cy = __ldg(p + 1), cz = __ldg(p + 2);
    if (t == 0) {
        s_gmax[0] = 0u; s_gmax[1] = 0u;
        s_best[0] = 0x7fffffff; s_best[1] = 0x7fffffff;
        float* o = out_qp + (size_t)b * NQ * 3;
        o[0] = cx; o[1] = cy; o[2] = cz;
    }
    __syncthreads();

    for (int it = 1; it < NQ; ++it) {
        const int buf = it & 1;
        const float nx = fneg_exact(cx), ny = fneg_exact(cy), nz = fneg_exact(cz);
        const u64 nx2 = pack2(nx, nx);
        const u64 ny2 = pack2(ny, ny);
        const u64 nz2 = pack2(nz, nz);

        float tmax = 0.0f;
#pragma unroll
        for (int pr = 0; pr < 16; pr++) {
            u64 dx2 = add2(PX[pr], nx2);            // x + (-c) == x - c exactly
            u64 dy2 = add2(PY[pr], ny2);
            u64 dz2 = add2(PZ[pr], nz2);
            u64 d2  = add2(add2(mul2(dx2, dx2), mul2(dy2, dy2)), mul2(dz2, dz2));
            float d0, d1; unpack2(d2, d0, d1);
            float n0 = fminf(dist[pr * 2 + 0], d0);
            float n1 = fminf(dist[pr * 2 + 1], d1);
            dist[pr * 2 + 0] = n0; dist[pr * 2 + 1] = n1;
            tmax = fmaxf(tmax, n0);
            tmax = fmaxf(tmax, n1);
        }

        const unsigned ut = __float_as_uint(tmax);
        const unsigned wm = __reduce_max_sync(0xffffffffu, ut);
        if ((t & 31) == 0) atomicMax(&s_gmax[buf], wm);
        __syncthreads();                            // bar1: gmax final

        const unsigned g = s_gmax[buf];
        if (ut == g) {                              // owner thread(s): rare
            int j = 0;
#pragma unroll
            for (int jj = 31; jj >= 0; jj--)        // downward => first match
                if (__float_as_uint(dist[jj]) == g) j = jj;
            atomicMin(&s_best[buf], t * 32 + j);
        }
        if (t == 0) { s_gmax[buf ^ 1] = 0u; s_best[buf ^ 1] = 0x7fffffff; }
        __syncthreads();                            // bar2: best final

        const int best = s_best[buf];
        const float* pb = p + (size_t)best * 3;     // uniform -> L1 broadcast
        cx = __ldg(pb + 0); cy = __ldg(pb + 1); cz = __ldg(pb + 2);
        if (t == 0) {
            float* o = out_qp + ((size_t)b * NQ + it) * 3;
            o[0] = cx; o[1] = cy; o[2] = cz;
        }
    }
}

// ---------------------------------------------------------------------------
// Kernel 2: ball query — R11 kernel verbatim. Warp per query, NO early exit
// (deep MLP), ballot + prefix-popc, exact arithmetic (plain subtract,
// __fmul_rn/__fadd_rn sum, no FMA contraction).
// R2 = float(double(0.1*0.1)) matches the weakly-typed JAX scalar.
// ---------------------------------------------------------------------------
__global__ void __launch_bounds__(256)
ball_kernel(const float* __restrict__ qp, float* __restrict__ out_idx)
{
    const int warp = threadIdx.x >> 5;
    const int lane = threadIdx.x & 31;
    const int gq   = blockIdx.x * 8 + warp;        // one query per warp
    const int b    = gq >> 11;                     // gq / NQ
    const float R2 = (float)(0.1 * 0.1);           // 0.00999999977648258f
    const float* sx = g_sx + (size_t)b * NPTS;
    const float* sy = g_sy + (size_t)b * NPTS;
    const float* sz = g_sz + (size_t)b * NPTS;

    __shared__ int s_wi[8][NK];

    const float qx = qp[(size_t)gq * 3 + 0];
    const float qy = qp[(size_t)gq * 3 + 1];
    const float qz = qp[(size_t)gq * 3 + 2];

    int cnt = 0;
    const unsigned lmask = (1u << lane) - 1u;
#pragma unroll 4
    for (int c = 0; c < NPTS / 32; c++) {
        const int i = c * 32 + lane;
        float dx = qx - __ldg(sx + i);
        float dy = qy - __ldg(sy + i);
        float dz = qz - __ldg(sz + i);
        float d  = __fadd_rn(__fadd_rn(__fmul_rn(dx, dx), __fmul_rn(dy, dy)),
                             __fmul_rn(dz, dz));
        const bool in = (d <= R2);
        const unsigned m = __ballot_sync(0xffffffffu, in);
        if (m) {
            const int slot = cnt + __popc(m & lmask);
            if (in && slot < NK) s_wi[warp][slot] = i;
            cnt += __popc(m);
        }
    }
    __syncwarp();
    const int cf    = cnt < NK ? cnt : NK;
    const int first = s_wi[warp][0];
    const int v     = (lane < cf) ? s_wi[warp][lane] : first;
    g_nidx[(size_t)gq * NK + lane]  = v;
    out_idx[(size_t)gq * NK + lane] = (float)v;
}

// ---------------------------------------------------------------------------
// Kernel 3: gather + write grouped outputs — R11 kernel verbatim.
// Warp per query (lane = k); grouped_features staged through shared
// (stride 19 conflict-free) and stored coalesced.
// ---------------------------------------------------------------------------
__global__ void __launch_bounds__(256)
gather_kernel(const float* __restrict__ feat, const float* __restrict__ qp,
              float* __restrict__ out)
{
    const int warp = threadIdx.x >> 5;
    const int lane = threadIdx.x & 31;
    const int gq   = blockIdx.x * 8 + warp;          // 0 .. BATCH*NQ-1
    const int b    = gq >> 11;

    __shared__ float s[8][NK * 19];

    const int idx = g_nidx[(size_t)gq * NK + lane];
    const size_t pb = (size_t)b * NPTS + idx;
    const float px = g_sx[pb];
    const float py = g_sy[pb];
    const float pz = g_sz[pb];

    const float qx = qp[(size_t)gq * 3 + 0];
    const float qy = qp[(size_t)gq * 3 + 1];
    const float qz = qp[(size_t)gq * 3 + 2];
    const float nx = px - qx, ny = py - qy, nz = pz - qz;

    const float4* f4 = (const float4*)(feat + pb * NF);
    const float4 f0 = f4[0], f1 = f4[1], f2 = f4[2], f3 = f4[3];

    float* sw = &s[warp][lane * 19];
    sw[0]  = nx;   sw[1]  = ny;   sw[2]  = nz;
    sw[3]  = f0.x; sw[4]  = f0.y; sw[5]  = f0.z; sw[6]  = f0.w;
    sw[7]  = f1.x; sw[8]  = f1.y; sw[9]  = f1.z; sw[10] = f1.w;
    sw[11] = f2.x; sw[12] = f2.y; sw[13] = f2.z; sw[14] = f2.w;
    sw[15] = f3.x; sw[16] = f3.y; sw[17] = f3.z; sw[18] = f3.w;
    __syncwarp();

    float* gf = out + GF_OFF + (size_t)gq * (NK * 19);
#pragma unroll
    for (int w = 0; w < 19; w++) {
        const int i = w * 32 + lane;
        gf[i] = s[warp][i];                           // coalesced
    }

    float* gpn = out + GPN_OFF + ((size_t)gq * NK + lane) * 3;
    gpn[0] = nx; gpn[1] = ny; gpn[2] = nz;

    float* gp = out + GP_OFF + ((size_t)gq * NK + lane) * 3;
    gp[0] = px; gp[1] = py; gp[2] = pz;
}

// ---------------------------------------------------------------------------
extern "C" void kernel_launch(void* const* d_in, const int* in_sizes, int n_in,
                              void* d_out, int out_size)
{
    const float* points   = (const float*)d_in[0];
    const float* features = (const float*)d_in[1];
    if (in_sizes[0] != BATCH * NPTS * 3) {
        const float* tmp = points; points = features; features = tmp;
    }
    float* out = (float*)d_out;

    transpose_kernel<<<(BATCH * NPTS + 255) / 256, 256>>>(points);
    fps_kernel<<<BATCH, 256>>>(points, out + QP_OFF);
    ball_kernel<<<BATCH * NQ / 8, 256>>>(out + QP_OFF, out + IDX_OFF);
    gather_kernel<<<BATCH * NQ / 8, 256>>>(features, out + QP_OFF, out);
}

// round 14
// speedup vs baseline: 1.1383x; 1.0601x over previous
#include <cuda_runtime.h>
#include <cuda_bf16.h>
#include <cstdint>

#define BATCH 8
#define NPTS  8192
#define NQ    2048
#define NK    32
#define NF    16

// Output layout: flattened float32 concat of the 5-tuple
static const size_t QP_OFF  = 0;                                   // 8*2048*3      = 49152
static const size_t GF_OFF  = 49152;                               // 8*2048*32*19  = 9961472
static const size_t IDX_OFF = 49152 + 9961472;                     // 10,010,624
static const size_t GPN_OFF = IDX_OFF + (size_t)BATCH*NQ*NK;       // 10,534,912
static const size_t GP_OFF  = GPN_OFF + (size_t)BATCH*NQ*NK*3;     // 12,107,776

__device__ int   g_nidx[BATCH * NQ * NK];
__device__ float g_sx[BATCH * NPTS];
__device__ float g_sy[BATCH * NPTS];
__device__ float g_sz[BATCH * NPTS];

// ---- packed f32x2 helpers (sm_103a): per-lane IEEE .rn, identical to scalar
typedef unsigned long long u64;
__device__ __forceinline__ u64 pack2(float lo, float hi) {
    u64 r; asm("mov.b64 %0, {%1, %2};" : "=l"(r) : "f"(lo), "f"(hi)); return r;
}
__device__ __forceinline__ void unpack2(u64 v, float& lo, float& hi) {
    asm("mov.b64 {%0, %1}, %2;" : "=f"(lo), "=f"(hi) : "l"(v));
}
__device__ __forceinline__ u64 add2(u64 a, u64 b) {
    u64 r; asm("add.rn.f32x2 %0, %1, %2;" : "=l"(r) : "l"(a), "l"(b)); return r;
}
__device__ __forceinline__ u64 mul2(u64 a, u64 b) {
    u64 r; asm("mul.rn.f32x2 %0, %1, %2;" : "=l"(r) : "l"(a), "l"(b)); return r;
}
__device__ __forceinline__ float fneg_exact(float x) {   // sign-bit flip (ALU)
    return __uint_as_float(__float_as_uint(x) ^ 0x80000000u);
}

// ---------------------------------------------------------------------------
// Kernel 0: AoS -> SoA transpose of points (one-time, ~4.5us).
// ---------------------------------------------------------------------------
__global__ void __launch_bounds__(256)
transpose_kernel(const float* __restrict__ pts)
{
    const int i = blockIdx.x * blockDim.x + threadIdx.x;
    if (i >= BATCH * NPTS) return;
    g_sx[i] = pts[(size_t)i * 3 + 0];
    g_sy[i] = pts[(size_t)i * 3 + 1];
    g_sz[i] = pts[(size_t)i * 3 + 2];
}

// ---------------------------------------------------------------------------
// Kernel 1: farthest point sampling — R11 kernel VERBATIM (measured optimum:
// 512 threads x 16 pts/thread; 1024 and 256 both measured slower).
// Exact semantics: d = ((dx*dx)+(dy*dy))+(dz*dz), each op .rn (no FMA),
// dist = min(dist, d), argmax with first-index tie-break:
//   REDUX.max -> lane0 atomicMax(s_gmax[buf]); bar1; owners (ut==g) resolve
//   first-j, atomicMin(s_best[buf]); t0 resets spares; bar2; all threads
//   LDG-broadcast pts[best] (uniform address, L1-resident).
// ---------------------------------------------------------------------------
__global__ void __launch_bounds__(512, 1)
fps_kernel(const float* __restrict__ pts, float* __restrict__ out_qp)
{
    const int b = blockIdx.x;
    const int t = threadIdx.x;
    const float* p = pts + (size_t)b * NPTS * 3;

    __shared__ unsigned s_gmax[2];
    __shared__ int      s_best[2];

    u64 PX[8], PY[8], PZ[8];
    float dist[16];
#pragma unroll
    for (int pr = 0; pr < 8; pr++) {
        int i0 = t * 16 + pr * 2;
        float x0 = p[i0 * 3 + 0], y0 = p[i0 * 3 + 1], z0 = p[i0 * 3 + 2];
        float x1 = p[i0 * 3 + 3], y1 = p[i0 * 3 + 4], z1 = p[i0 * 3 + 5];
        PX[pr] = pack2(x0, x1); PY[pr] = pack2(y0, y1); PZ[pr] = pack2(z0, z1);
        dist[pr * 2] = 1e10f; dist[pr * 2 + 1] = 1e10f;
    }
    float cx = __ldg(p + 0), cy = __ldg(p + 1), cz = __ldg(p + 2);
    if (t == 0) {
        s_gmax[0] = 0u; s_gmax[1] = 0u;
        s_best[0] = 0x7fffffff; s_best[1] = 0x7fffffff;
        float* o = out_qp + (size_t)b * NQ * 3;
        o[0] = cx; o[1] = cy; o[2] = cz;
    }
    __syncthreads();

    for (int it = 1; it < NQ; ++it) {
        const int buf = it & 1;
        const float nx = fneg_exact(cx), ny = fneg_exact(cy), nz = fneg_exact(cz);
        const u64 nx2 = pack2(nx, nx);
        const u64 ny2 = pack2(ny, ny);
        const u64 nz2 = pack2(nz, nz);

        float tmax = 0.0f;
#pragma unroll
        for (int pr = 0; pr < 8; pr++) {
            u64 dx2 = add2(PX[pr], nx2);            // x + (-c) == x - c exactly
            u64 dy2 = add2(PY[pr], ny2);
            u64 dz2 = add2(PZ[pr], nz2);
            u64 d2  = add2(add2(mul2(dx2, dx2), mul2(dy2, dy2)), mul2(dz2, dz2));
            float d0, d1; unpack2(d2, d0, d1);
            float n0 = fminf(dist[pr * 2 + 0], d0);
            float n1 = fminf(dist[pr * 2 + 1], d1);
            dist[pr * 2 + 0] = n0; dist[pr * 2 + 1] = n1;
            tmax = fmaxf(tmax, n0);
            tmax = fmaxf(tmax, n1);
        }

        const unsigned ut = __float_as_uint(tmax);
        const unsigned wm = __reduce_max_sync(0xffffffffu, ut);
        if ((t & 31) == 0) atomicMax(&s_gmax[buf], wm);
        __syncthreads();                            // bar1: gmax final

        const unsigned g = s_gmax[buf];
        if (ut == g) {                              // owner thread(s): rare
            int j = 0;
#pragma unroll
            for (int jj = 15; jj >= 0; jj--)        // downward => first match
                if (__float_as_uint(dist[jj]) == g) j = jj;
            atomicMin(&s_best[buf], t * 16 + j);
        }
        if (t == 0) { s_gmax[buf ^ 1] = 0u; s_best[buf ^ 1] = 0x7fffffff; }
        __syncthreads();                            // bar2: best final

        const int best = s_best[buf];
        const float* pb = p + (size_t)best * 3;     // uniform -> L1 broadcast
        cx = __ldg(pb + 0); cy = __ldg(pb + 1); cz = __ldg(pb + 2);
        if (t == 0) {
            float* o = out_qp + ((size_t)b * NQ + it) * 3;
            o[0] = cx; o[1] = cy; o[2] = cz;
        }
    }
}

// ---------------------------------------------------------------------------
// Kernel 2: ball query — smem-tiled. The warp-streaming version moved
// 16384 warps x 96KB = 1.5GB through L2 (~134us at the LTS cap). Each CTA
// (8 warps = 8 queries, one batch) now cooperatively stages the batch's
// points in 4 x 2048-pt smem tiles (24KB) and all warps scan from smem:
// L2 traffic drops 8x, LDS reads are conflict-free (tx[c*32+lane]).
// Values pass through smem bit-unchanged; tiles+chunks scanned in index
// order -> identical hit set/order. Exact arithmetic: plain subtract,
// __fmul_rn/__fadd_rn sum (no FMA contraction).
// R2 = float(double(0.1*0.1)) matches the weakly-typed JAX scalar.
// ---------------------------------------------------------------------------
#define TILE_PTS 2048
__global__ void __launch_bounds__(256)
ball_kernel(const float* __restrict__ qp, float* __restrict__ out_idx)
{
    const int warp = threadIdx.x >> 5;
    const int lane = threadIdx.x & 31;
    const int tid  = threadIdx.x;
    const int gq   = blockIdx.x * 8 + warp;        // one query per warp
    const int b    = gq >> 11;                     // gq / NQ (uniform per CTA)
    const float R2 = (float)(0.1 * 0.1);           // 0.00999999977648258f
    const float* sx = g_sx + (size_t)b * NPTS;
    const float* sy = g_sy + (size_t)b * NPTS;
    const float* sz = g_sz + (size_t)b * NPTS;

    __shared__ float tx[TILE_PTS], ty[TILE_PTS], tz[TILE_PTS];
    __shared__ int s_wi[8][NK];

    const float qx = qp[(size_t)gq * 3 + 0];
    const float qy = qp[(size_t)gq * 3 + 1];
    const float qz = qp[(size_t)gq * 3 + 2];

    int cnt = 0;
    const unsigned lmask = (1u << lane) - 1u;

    for (int tile = 0; tile < NPTS / TILE_PTS; tile++) {
        const int base = tile * TILE_PTS;
        __syncthreads();                           // previous tile consumed
#pragma unroll
        for (int k = 0; k < TILE_PTS / 256; k++) { // cooperative fill
            const int i = k * 256 + tid;
            tx[i] = sx[base + i];
            ty[i] = sy[base + i];
            tz[i] = sz[base + i];
        }
        __syncthreads();                           // tile ready

#pragma unroll 4
        for (int c = 0; c < TILE_PTS / 32; c++) {
            const int i = c * 32 + lane;           // conflict-free LDS
            float dx = qx - tx[i];
            float dy = qy - ty[i];
            float dz = qz - tz[i];
            float d  = __fadd_rn(__fadd_rn(__fmul_rn(dx, dx), __fmul_rn(dy, dy)),
                                 __fmul_rn(dz, dz));
            const bool in = (d <= R2);
            const unsigned m = __ballot_sync(0xffffffffu, in);
            if (m) {
                const int slot = cnt + __popc(m & lmask);
                if (in && slot < NK) s_wi[warp][slot] = base + i;
                cnt += __popc(m);
            }
        }
    }
    __syncwarp();
    const int cf    = cnt < NK ? cnt : NK;
    const int first = s_wi[warp][0];
    const int v     = (lane < cf) ? s_wi[warp][lane] : first;
    g_nidx[(size_t)gq * NK + lane]  = v;
    out_idx[(size_t)gq * NK + lane] = (float)v;
}

// ---------------------------------------------------------------------------
// Kernel 3: gather + write grouped outputs — R11 kernel verbatim.
// Warp per query (lane = k); grouped_features staged through shared
// (stride 19 conflict-free) and stored coalesced.
// ---------------------------------------------------------------------------
__global__ void __launch_bounds__(256)
gather_kernel(const float* __restrict__ feat, const float* __restrict__ qp,
              float* __restrict__ out)
{
    const int warp = threadIdx.x >> 5;
    const int lane = threadIdx.x & 31;
    const int gq   = blockIdx.x * 8 + warp;          // 0 .. BATCH*NQ-1
    const int b    = gq >> 11;

    __shared__ float s[8][NK * 19];

    const int idx = g_nidx[(size_t)gq * NK + lane];
    const size_t pb = (size_t)b * NPTS + idx;
    const float px = g_sx[pb];
    const float py = g_sy[pb];
    const float pz = g_sz[pb];

    const float qx = qp[(size_t)gq * 3 + 0];
    const float qy = qp[(size_t)gq * 3 + 1];
    const float qz = qp[(size_t)gq * 3 + 2];
    const float nx = px - qx, ny = py - qy, nz = pz - qz;

    const float4* f4 = (const float4*)(feat + pb * NF);
    const float4 f0 = f4[0], f1 = f4[1], f2 = f4[2], f3 = f4[3];

    float* sw = &s[warp][lane * 19];
    sw[0]  = nx;   sw[1]  = ny;   sw[2]  = nz;
    sw[3]  = f0.x; sw[4]  = f0.y; sw[5]  = f0.z; sw[6]  = f0.w;
    sw[7]  = f1.x; sw[8]  = f1.y; sw[9]  = f1.z; sw[10] = f1.w;
    sw[11] = f2.x; sw[12] = f2.y; sw[13] = f2.z; sw[14] = f2.w;
    sw[15] = f3.x; sw[16] = f3.y; sw[17] = f3.z; sw[18] = f3.w;
    __syncwarp();

    float* gf = out + GF_OFF + (size_t)gq * (NK * 19);
#pragma unroll
    for (int w = 0; w < 19; w++) {
        const int i = w * 32 + lane;
        gf[i] = s[warp][i];                           // coalesced
    }

    float* gpn = out + GPN_OFF + ((size_t)gq * NK + lane) * 3;
    gpn[0] = nx; gpn[1] = ny; gpn[2] = nz;

    float* gp = out + GP_OFF + ((size_t)gq * NK + lane) * 3;
    gp[0] = px; gp[1] = py; gp[2] = pz;
}

// ---------------------------------------------------------------------------
extern "C" void kernel_launch(void* const* d_in, const int* in_sizes, int n_in,
                              void* d_out, int out_size)
{
    const float* points   = (const float*)d_in[0];
    const float* features = (const float*)d_in[1];
    if (in_sizes[0] != BATCH * NPTS * 3) {
        const float* tmp = points; points = features; features = tmp;
    }
    float* out = (float*)d_out;

    transpose_kernel<<<(BATCH * NPTS + 255) / 256, 256>>>(points);
    fps_kernel<<<BATCH, 512>>>(points, out + QP_OFF);
    ball_kernel<<<BATCH * NQ / 8, 256>>>(out + QP_OFF, out + IDX_OFF);
    gather_kernel<<<BATCH * NQ / 8, 256>>>(features, out + QP_OFF, out);
}